// round 1
// baseline (speedup 1.0000x reference)
#include <cuda_runtime.h>
#include <math.h>

// Qwen3VLMoeTextTopKRouter: logits = x @ W^T, softmax, top-8, renorm, dense scatter.
// Output layout assumed: [scores (T*E) f32][top_idx (T*K) as f32], gated on out_size.

namespace {
constexpr int TOKENS = 32768;
constexpr int HID    = 2048;
constexpr int NE     = 128;
constexpr int TOPK   = 8;

constexpr int BM = 128;   // tokens per CTA
constexpr int BN = 128;   // experts (== NE, full width)
constexpr int BK = 16;
constexpr int NTHREADS = 256;
constexpr int LPAD = 4;   // logits smem row pad
constexpr int GEMM_SMEM_FLOATS = 2 * BK * BM + 2 * BK * BN;        // 8192 floats = 32 KB
constexpr int LOGIT_SMEM_FLOATS = BM * (BN + LPAD);                // 16896 floats = 66 KB
constexpr int SMEM_BYTES = (LOGIT_SMEM_FLOATS > GEMM_SMEM_FLOATS ?
                            LOGIT_SMEM_FLOATS : GEMM_SMEM_FLOATS) * 4; // 67584
}

__global__ __launch_bounds__(NTHREADS, 1)
void router_kernel(const float* __restrict__ x, const float* __restrict__ w,
                   float* __restrict__ scores, float* __restrict__ idx_out,
                   int write_idx)
{
    extern __shared__ float smem[];
    float* As = smem;                 // [2][BK][BM] transposed (k-major)
    float* Bs = smem + 2 * BK * BM;   // [2][BK][BN] transposed

    const int tid = threadIdx.x;
    const int tx  = tid & 15;         // expert-tile column group
    const int ty  = tid >> 4;         // token-tile row group
    const int m0  = blockIdx.x * BM;

    // global loader mapping: 512 float4 per tile per matrix, 2 per thread
    const int lrow = tid >> 2;        // 0..63
    const int lcol = tid & 3;         // 0..3 (float4 slot within BK=16 floats)

    const float* xg = x + (size_t)m0 * HID;

    float c[8][8];
#pragma unroll
    for (int i = 0; i < 8; i++)
#pragma unroll
        for (int j = 0; j < 8; j++) c[i][j] = 0.f;

    float4 ra[2], rb[2];

    // ---- prologue: load tile 0 ----
#pragma unroll
    for (int q = 0; q < 2; q++) {
        int r = lrow + q * 64;
        ra[q] = *(const float4*)(xg + (size_t)r * HID + lcol * 4);
        rb[q] = *(const float4*)(w  + (size_t)r * HID + lcol * 4);
    }
    {
        float* A0 = As;
        float* B0 = Bs;
#pragma unroll
        for (int q = 0; q < 2; q++) {
            int r  = lrow + q * 64;
            int k4 = lcol * 4;
            A0[(k4 + 0) * BM + r] = ra[q].x;
            A0[(k4 + 1) * BM + r] = ra[q].y;
            A0[(k4 + 2) * BM + r] = ra[q].z;
            A0[(k4 + 3) * BM + r] = ra[q].w;
            B0[(k4 + 0) * BN + r] = rb[q].x;
            B0[(k4 + 1) * BN + r] = rb[q].y;
            B0[(k4 + 2) * BN + r] = rb[q].z;
            B0[(k4 + 3) * BN + r] = rb[q].w;
        }
    }
    __syncthreads();

    // ---- mainloop: double-buffered over K ----
    const int NT = HID / BK;  // 128
    for (int kt = 0; kt < NT; kt++) {
        const int cur = kt & 1;
        if (kt + 1 < NT) {
            const int koff = (kt + 1) * BK;
#pragma unroll
            for (int q = 0; q < 2; q++) {
                int r = lrow + q * 64;
                ra[q] = *(const float4*)(xg + (size_t)r * HID + koff + lcol * 4);
                rb[q] = *(const float4*)(w  + (size_t)r * HID + koff + lcol * 4);
            }
        }
        const float* A = As + cur * BK * BM;
        const float* B = Bs + cur * BK * BN;
#pragma unroll
        for (int kk = 0; kk < BK; kk++) {
            float af[8], bf[8];
            *(float4*)&af[0] = *(const float4*)&A[kk * BM + ty * 8];
            *(float4*)&af[4] = *(const float4*)&A[kk * BM + ty * 8 + 4];
            *(float4*)&bf[0] = *(const float4*)&B[kk * BN + tx * 8];
            *(float4*)&bf[4] = *(const float4*)&B[kk * BN + tx * 8 + 4];
#pragma unroll
            for (int i = 0; i < 8; i++)
#pragma unroll
                for (int j = 0; j < 8; j++)
                    c[i][j] = fmaf(af[i], bf[j], c[i][j]);
        }
        if (kt + 1 < NT) {
            const int nxt = cur ^ 1;
            float* A1 = As + nxt * BK * BM;
            float* B1 = Bs + nxt * BK * BN;
#pragma unroll
            for (int q = 0; q < 2; q++) {
                int r  = lrow + q * 64;
                int k4 = lcol * 4;
                A1[(k4 + 0) * BM + r] = ra[q].x;
                A1[(k4 + 1) * BM + r] = ra[q].y;
                A1[(k4 + 2) * BM + r] = ra[q].z;
                A1[(k4 + 3) * BM + r] = ra[q].w;
                B1[(k4 + 0) * BN + r] = rb[q].x;
                B1[(k4 + 1) * BN + r] = rb[q].y;
                B1[(k4 + 2) * BN + r] = rb[q].z;
                B1[(k4 + 3) * BN + r] = rb[q].w;
            }
        }
        __syncthreads();
    }

    // ---- epilogue: logits -> smem (reuse), then per-token top-8 ----
    float* L = smem;  // [BM][BN + LPAD]
#pragma unroll
    for (int i = 0; i < 8; i++) {
        int row = ty * 8 + i;
        *(float4*)&L[row * (BN + LPAD) + tx * 8]     =
            make_float4(c[i][0], c[i][1], c[i][2], c[i][3]);
        *(float4*)&L[row * (BN + LPAD) + tx * 8 + 4] =
            make_float4(c[i][4], c[i][5], c[i][6], c[i][7]);
    }
    __syncthreads();

    const int warp = tid >> 5;
    const int lane = tid & 31;

    for (int tl = warp * 16; tl < warp * 16 + 16; tl++) {
        const float* row = &L[tl * (BN + LPAD)];
        float v[4];
#pragma unroll
        for (int k = 0; k < 4; k++) v[k] = row[lane + 32 * k];

        // 8 rounds of warp-wide argmax; tie-break = lower index (matches lax.top_k)
        float topv[8];
        int   topi[8];
#pragma unroll
        for (int r = 0; r < 8; r++) {
            float bv = -INFINITY;
            int   bi = 0x7fffffff;
#pragma unroll
            for (int k = 0; k < 4; k++) {
                if (v[k] > bv) { bv = v[k]; bi = lane + 32 * k; }
            }
#pragma unroll
            for (int off = 16; off > 0; off >>= 1) {
                float ov = __shfl_xor_sync(0xffffffffu, bv, off);
                int   oi = __shfl_xor_sync(0xffffffffu, bi, off);
                if (ov > bv || (ov == bv && oi < bi)) { bv = ov; bi = oi; }
            }
            topv[r] = bv;
            topi[r] = bi;
#pragma unroll
            for (int k = 0; k < 4; k++)
                if (lane + 32 * k == bi) v[k] = -INFINITY;
        }

        // renormalized top-k probs: exp(l - max) / sum_top8 exp(l - max)
        const float m = topv[0];
        float ev[8];
        float s = 0.f;
#pragma unroll
        for (int r = 0; r < 8; r++) { ev[r] = expf(topv[r] - m); s += ev[r]; }
        const float inv = 1.f / s;

        const int gt = m0 + tl;
        float* srow = scores + (size_t)gt * NE;
#pragma unroll
        for (int k = 0; k < 4; k++) {
            const int e = lane + 32 * k;
            float val = 0.f;
#pragma unroll
            for (int r = 0; r < 8; r++)
                if (topi[r] == e) val = ev[r] * inv;
            srow[e] = val;
        }
        if (write_idx && lane < TOPK)
            idx_out[(size_t)gt * TOPK + lane] = (float)topi[lane];
    }
}

extern "C" void kernel_launch(void* const* d_in, const int* in_sizes, int n_in,
                              void* d_out, int out_size)
{
    const float* x = (const float*)d_in[0];
    const float* w = (const float*)d_in[1];
    // defensive: detect swapped input order via element counts
    if (n_in >= 2 && in_sizes[0] == NE * HID && in_sizes[1] == TOKENS * HID) {
        x = (const float*)d_in[1];
        w = (const float*)d_in[0];
    }

    float* scores  = (float*)d_out;
    float* idx_out = scores + (size_t)TOKENS * NE;
    const int write_idx = (out_size >= TOKENS * NE + TOKENS * TOPK) ? 1 : 0;

    cudaFuncSetAttribute(router_kernel,
                         cudaFuncAttributeMaxDynamicSharedMemorySize, SMEM_BYTES);
    router_kernel<<<TOKENS / BM, NTHREADS, SMEM_BYTES>>>(x, w, scores, idx_out,
                                                         write_idx);
}